// round 15
// baseline (speedup 1.0000x reference)
#include <cuda_runtime.h>
#include <cuda_fp16.h>
#include <math.h>
#include <stdint.h>

#define Bsz   8
#define Lseq  8192
#define Hdim  1024
#define NS    64
#define NTAP  48
#define M_TOT (Bsz * Lseq)   // 65536

typedef unsigned short ushort_t;

// ---------------- scratch ----------------
__device__ float    g_u[(size_t)M_TOT * NS];        // 16 MB
__device__ ushort_t g_ch[(size_t)M_TOT * NS];       // 8 MB  conv (fp16 bits)
__device__ ushort_t g_pinF[NS * Hdim];              // [n][k] fp16
__device__ ushort_t g_poutF[Hdim * NS];             // [n][k] fp16
__device__ float g_kre[NTAP * NS];
__device__ float g_kim[NTAP * NS];

__device__ __forceinline__ uint32_t pack2h(__half a, __half b) {
    return (uint32_t)__half_as_ushort(a) | ((uint32_t)__half_as_ushort(b) << 16);
}
// f32.f16.f16.f32 HMMA (sm_80+, legal under compute_103)
__device__ __forceinline__ void mma16816h(float* c, const uint32_t* a, const uint32_t* b) {
    asm volatile(
        "mma.sync.aligned.m16n8k16.row.col.f32.f16.f16.f32 "
        "{%0,%1,%2,%3}, {%4,%5,%6,%7}, {%8,%9}, {%0,%1,%2,%3};"
        : "+f"(c[0]), "+f"(c[1]), "+f"(c[2]), "+f"(c[3])
        : "r"(a[0]), "r"(a[1]), "r"(a[2]), "r"(a[3]), "r"(b[0]), "r"(b[1]));
}
__device__ __forceinline__ uint32_t cvta_smem(const void* p) {
    uint32_t a;
    asm("{ .reg .u64 t; cvta.to.shared.u64 t, %1; cvt.u32.u64 %0, t; }" : "=r"(a) : "l"(p));
    return a;
}
__device__ __forceinline__ void ldsm_x4(uint32_t* r, uint32_t addr) {
    asm volatile("ldmatrix.sync.aligned.m8n8.x4.shared.b16 {%0,%1,%2,%3}, [%4];"
                 : "=r"(r[0]), "=r"(r[1]), "=r"(r[2]), "=r"(r[3]) : "r"(addr));
}

// ---------------- taps ----------------
__global__ void taps_kernel(const float* __restrict__ freq, const float* __restrict__ dec) {
    int d = blockIdx.x;
    int n = threadIdx.x;
    double rho = -exp((double)dec[n]);
    double th  = (double)freq[n];
    double mag = exp(rho * (double)d);
    double ph  = th * (double)d;
    g_kre[d * NS + n] = (float)(mag * cos(ph));
    g_kim[d * NS + n] = (float)(mag * sin(ph));
}

// ---------------- projection planes: single fp16, [n][k] ----------------
__global__ void __launch_bounds__(256) prep_planes(const float* __restrict__ pin,
                                                   const float* __restrict__ pout) {
    int idx = blockIdx.x * 256 + threadIdx.x;   // 0..131071
    if (idx < NS * Hdim) {                      // pin: [n<64][k<1024]
        int n = idx >> 10, k = idx & 1023;
        g_pinF[idx] = __half_as_ushort(__float2half(pin[(size_t)k * NS + n]));
    } else {                                    // pout: [n<1024][k<64]
        int j = idx - NS * Hdim;
        int n = j >> 6, k = j & 63;
        g_poutF[j] = __half_as_ushort(__float2half(pout[(size_t)k * Hdim + n]));
    }
}

#define RS 80   // gemmA: 64B data + 16B pad

// ============ GEMM A (HMMA fp16 1-term): g_u[M,64] = input[M,1024] @ P_in[1024,64] ============
// smem: Af(10240) Bf(5120) = 15360 static
__global__ void __launch_bounds__(256) gemmA_mma(const float* __restrict__ A) {
    __shared__ char sm[15360];
    char* Af = sm;
    char* Bf = sm + 10240;

    int tid = threadIdx.x;
    int m0  = blockIdx.x * 128;
    int w   = tid >> 5, l = tid & 31;
    int wm  = w >> 1, wn = w & 1;          // warp tile 32m x 32n
    int lr  = l >> 2, lc = l & 3;
    int lrow = l & 15, lhalf = (l >> 4) * 16;

    int ra[4], qa[4];
#pragma unroll
    for (int t = 0; t < 4; ++t) { int idx = t * 256 + tid; ra[t] = idx >> 3; qa[t] = idx & 7; }
    int rB = tid >> 2, qB = tid & 3;

    uint32_t smb = cvta_smem(sm);

    float acc[2][4][4];
#pragma unroll
    for (int i = 0; i < 2; i++)
#pragma unroll
        for (int j = 0; j < 4; j++)
#pragma unroll
            for (int q = 0; q < 4; q++) acc[i][j][q] = 0.f;

    // prologue: prefetch chunk 0
    float4 areg[4];
    uint4 bfreg;
#pragma unroll
    for (int t = 0; t < 4; ++t)
        areg[t] = *(const float4*)&A[(size_t)(m0 + ra[t]) * Hdim + qa[t] * 4];
    bfreg = *(const uint4*)&g_pinF[rB * Hdim + qB * 8];

    for (int c = 0; c < 32; ++c) {
        // STS current chunk (single fp16 plane)
#pragma unroll
        for (int t = 0; t < 4; ++t) {
            uint32_t p01 = pack2h(__float2half(areg[t].x), __float2half(areg[t].y));
            uint32_t p23 = pack2h(__float2half(areg[t].z), __float2half(areg[t].w));
            *(uint2*)(Af + ra[t] * RS + qa[t] * 8) = make_uint2(p01, p23);
        }
        *(uint4*)(Bf + rB * RS + qB * 16) = bfreg;
        __syncthreads();

        // prefetch next chunk (overlaps with MMA below)
        if (c < 31) {
            int k1 = (c + 1) * 32;
#pragma unroll
            for (int t = 0; t < 4; ++t)
                areg[t] = *(const float4*)&A[(size_t)(m0 + ra[t]) * Hdim + k1 + qa[t] * 4];
            bfreg = *(const uint4*)&g_pinF[rB * Hdim + k1 + qB * 8];
        }

#pragma unroll
        for (int ks = 0; ks < 2; ++ks) {
            int kb = ks * 32;
            uint32_t af[2][4];
#pragma unroll
            for (int mt = 0; mt < 2; ++mt) {
                uint32_t off = (uint32_t)((wm * 32 + mt * 16 + lrow) * RS + kb + lhalf);
                ldsm_x4(af[mt], smb + off);
            }
#pragma unroll
            for (int nt = 0; nt < 4; ++nt) {
                int n0 = wn * 32 + nt * 8 + lr;
                int co = kb + lc * 4;
                uint32_t bf[2];
                bf[0] = *(const uint32_t*)(Bf + n0 * RS + co);
                bf[1] = *(const uint32_t*)(Bf + n0 * RS + co + 16);
#pragma unroll
                for (int mt = 0; mt < 2; ++mt)
                    mma16816h(acc[mt][nt], af[mt], bf);
            }
        }
        __syncthreads();
    }
#pragma unroll
    for (int mt = 0; mt < 2; ++mt) {
        size_t mrow = (size_t)m0 + wm * 32 + mt * 16 + lr;
#pragma unroll
        for (int nt = 0; nt < 4; ++nt) {
            int n = wn * 32 + nt * 8 + lc * 2;
            *(float2*)&g_u[mrow * NS + n]       = make_float2(acc[mt][nt][0], acc[mt][nt][1]);
            *(float2*)&g_u[(mrow + 8) * NS + n] = make_float2(acc[mt][nt][2], acc[mt][nt][3]);
        }
    }
}

// ---------------- FIR (NTAP=48, TL=64) -> single fp16 plane; folded final-state ----------------
#define TL  64
#define WIN (TL + NTAP)   // 112 rows
__global__ void __launch_bounds__(256) fir_kernel(const float* __restrict__ init_state,
                                                  float* __restrict__ outp, int mode) {
    __shared__ float us[WIN * NS];
    int b    = blockIdx.x >> 7;
    int lblk = blockIdx.x & 127;
    int l0   = lblk * TL;
    int base_i = (l0 + 1) - (NTAP - 1);
    int tid  = threadIdx.x;

    for (int idx = tid; idx < WIN * NS; idx += 256) {
        int row = idx >> 6;
        int n   = idx & 63;
        int i   = base_i + row;
        float v;
        if (i < 0)        v = 0.f;
        else if (i == 0)  v = init_state[b * NS + n];
        else              v = g_u[((size_t)b * Lseq + (i - 1)) * NS + n];
        us[idx] = v;
    }
    __syncthreads();

    int n  = tid & 63;
    int lt = tid >> 6;
#pragma unroll
    for (int g = 0; g < 2; ++g) {
        int lb  = lt * 16 + g * 8;
        int off = lb + NTAP - 1;
        float acc[8];
#pragma unroll
        for (int r = 0; r < 8; r++) acc[r] = 0.f;
#pragma unroll
        for (int dc = 0; dc < NTAP; dc += 8) {
            float kk[8];
#pragma unroll
            for (int t = 0; t < 8; t++) kk[t] = g_kre[(dc + t) * NS + n];
            float uu[15];
#pragma unroll
            for (int t = 0; t < 15; t++) uu[t] = us[(off - dc - 7 + t) * NS + n];
#pragma unroll
            for (int d = 0; d < 8; ++d)
#pragma unroll
                for (int r = 0; r < 8; r++) acc[r] += kk[d] * uu[7 + r - d];
        }
#pragma unroll
        for (int r = 0; r < 8; r++) {
            size_t o = ((size_t)b * Lseq + l0 + lb + r) * NS + n;
            g_ch[o] = __half_as_ushort(__float2half(acc[r]));
        }
    }

    // folded final state s_L (complex) -> tail of d_out (full fp32 path)
    if (lblk == 127 && mode != 0 && tid < 64) {
        float re = 0.f, im = 0.f;
#pragma unroll 4
        for (int d = 0; d < NTAP; ++d) {
            float u = us[(Lseq - d - base_i) * NS + tid];
            re += g_kre[d * NS + tid] * u;
            im += g_kim[d * NS + tid] * u;
        }
        float* base = outp + (size_t)M_TOT * Hdim;
        if (mode == 2) {
            base[((size_t)b * NS + tid) * 2 + 0] = re;
            base[((size_t)b * NS + tid) * 2 + 1] = im;
        } else {
            base[(size_t)b * NS + tid] = re;
        }
    }
}

// ============ GEMM B (HMMA fp16 1-term, single K-pass): out = conv @ P_out ============
// smem: Af(18432) Bf(18432) = 36864; RS2=144
#define RS2 144
#define GB_SMEM (2 * 128 * RS2)   // 36864
__global__ void __launch_bounds__(256, 2) gemmB_mma(float* __restrict__ C) {
    extern __shared__ char dsm[];
    int tid = threadIdx.x;
    int n0c = blockIdx.x * 128;
    int m0  = blockIdx.y * 128;
    int w   = tid >> 5, l = tid & 31;
    int wm  = w >> 1, wn = w & 1;          // warp tile 32m x 64n
    int lr  = l >> 2, lc = l & 3;
    int lrow = l & 15, lhalf = (l >> 4) * 16;

    char* Af = dsm;
    char* Bf = dsm + 18432;
    uint32_t smb = cvta_smem(dsm);

    float acc[2][8][4];
#pragma unroll
    for (int i = 0; i < 2; i++)
#pragma unroll
        for (int j = 0; j < 8; j++)
#pragma unroll
            for (int q = 0; q < 4; q++) acc[i][j][q] = 0.f;

    // staging: full K=64; pure uint4 copies (2 planes)
#pragma unroll
    for (int t = 0; t < 4; ++t) {
        int idx = t * 256 + tid;
        int r = idx >> 3, q = idx & 7;
        *(uint4*)(Af + r * RS2 + q * 16) = *(const uint4*)&g_ch[(size_t)(m0 + r) * NS + q * 8];
        *(uint4*)(Bf + r * RS2 + q * 16) = *(const uint4*)&g_poutF[(size_t)(n0c + r) * NS + q * 8];
    }
    __syncthreads();

#pragma unroll
    for (int kstep = 0; kstep < 4; ++kstep) {
        int kb = kstep * 32;   // byte offset of 16-element k group
        uint32_t af[2][4];
#pragma unroll
        for (int mt = 0; mt < 2; ++mt) {
            uint32_t off = (uint32_t)((wm * 32 + mt * 16 + lrow) * RS2 + kb + lhalf);
            ldsm_x4(af[mt], smb + off);
        }
#pragma unroll
        for (int nt = 0; nt < 8; ++nt) {
            int n0 = wn * 64 + nt * 8 + lr;
            int co = kb + lc * 4;
            uint32_t bf[2];
            bf[0] = *(const uint32_t*)(Bf + n0 * RS2 + co);
            bf[1] = *(const uint32_t*)(Bf + n0 * RS2 + co + 16);
#pragma unroll
            for (int mt = 0; mt < 2; ++mt)
                mma16816h(acc[mt][nt], af[mt], bf);
        }
    }
#pragma unroll
    for (int mt = 0; mt < 2; ++mt) {
        size_t mrow = (size_t)m0 + wm * 32 + mt * 16 + lr;
#pragma unroll
        for (int nt = 0; nt < 8; ++nt) {
            int n = n0c + wn * 64 + nt * 8 + lc * 2;
            *(float2*)&C[mrow * Hdim + n]       = make_float2(acc[mt][nt][0], acc[mt][nt][1]);
            *(float2*)&C[(mrow + 8) * Hdim + n] = make_float2(acc[mt][nt][2], acc[mt][nt][3]);
        }
    }
}

// ---------------- launch ----------------
extern "C" void kernel_launch(void* const* d_in, const int* in_sizes, int n_in,
                              void* d_out, int out_size) {
    const float* input = (const float*)d_in[0];
    const float* init  = (const float*)d_in[1];
    const float* pin   = (const float*)d_in[2];
    const float* pout  = (const float*)d_in[3];
    const float* freq  = (const float*)d_in[4];
    const float* dec   = (const float*)d_in[5];
    float* out = (float*)d_out;

    cudaFuncSetAttribute(gemmB_mma, cudaFuncAttributeMaxDynamicSharedMemorySize, GB_SMEM);

    long long tail = (long long)out_size - (long long)M_TOT * Hdim;
    int mode = 0;
    if (tail >= (long long)Bsz * NS * 2)  mode = 2;
    else if (tail >= (long long)Bsz * NS) mode = 1;

    taps_kernel<<<NTAP, NS>>>(freq, dec);
    prep_planes<<<512, 256>>>(pin, pout);
    gemmA_mma<<<M_TOT / 128, 256>>>(input);
    fir_kernel<<<Bsz * (Lseq / TL), 256>>>(init, out, mode);
    gemmB_mma<<<dim3(Hdim / 128, M_TOT / 128), 256, GB_SMEM>>>(out);
}

// round 16
// speedup vs baseline: 1.2991x; 1.2991x over previous
#include <cuda_runtime.h>
#include <cuda_fp16.h>
#include <math.h>
#include <stdint.h>

#define Bsz   8
#define Lseq  8192
#define Hdim  1024
#define NS    64
#define NTAP  48
#define M_TOT (Bsz * Lseq)   // 65536

typedef unsigned short ushort_t;

// ---------------- scratch ----------------
// Layout matches round-14 exactly: g_u, g_ch, [8MB slot], planes, taps.
// g_pad occupies the address range round-14's g_cl held; FIR's g_u-read /
// g_ch-write stream alignment (L2 slice hash) is preserved.
__device__ float    g_u[(size_t)M_TOT * NS];        // 16 MB
__device__ ushort_t g_ch[(size_t)M_TOT * NS];       // 8 MB  conv (fp16 bits)
__device__ ushort_t g_pad[(size_t)M_TOT * NS];      // 8 MB  layout placeholder
__device__ ushort_t g_pinF[NS * Hdim];              // [n][k] fp16
__device__ ushort_t g_poutF[Hdim * NS];             // [n][k] fp16
__device__ float g_kre[NTAP * NS];
__device__ float g_kim[NTAP * NS];

__device__ __forceinline__ uint32_t pack2h(__half a, __half b) {
    return (uint32_t)__half_as_ushort(a) | ((uint32_t)__half_as_ushort(b) << 16);
}
// f32.f16.f16.f32 HMMA (sm_80+, legal under compute_103)
__device__ __forceinline__ void mma16816h(float* c, const uint32_t* a, const uint32_t* b) {
    asm volatile(
        "mma.sync.aligned.m16n8k16.row.col.f32.f16.f16.f32 "
        "{%0,%1,%2,%3}, {%4,%5,%6,%7}, {%8,%9}, {%0,%1,%2,%3};"
        : "+f"(c[0]), "+f"(c[1]), "+f"(c[2]), "+f"(c[3])
        : "r"(a[0]), "r"(a[1]), "r"(a[2]), "r"(a[3]), "r"(b[0]), "r"(b[1]));
}
__device__ __forceinline__ uint32_t cvta_smem(const void* p) {
    uint32_t a;
    asm("{ .reg .u64 t; cvta.to.shared.u64 t, %1; cvt.u32.u64 %0, t; }" : "=r"(a) : "l"(p));
    return a;
}
__device__ __forceinline__ void ldsm_x4(uint32_t* r, uint32_t addr) {
    asm volatile("ldmatrix.sync.aligned.m8n8.x4.shared.b16 {%0,%1,%2,%3}, [%4];"
                 : "=r"(r[0]), "=r"(r[1]), "=r"(r[2]), "=r"(r[3]) : "r"(addr));
}

// ---------------- taps ----------------
__global__ void taps_kernel(const float* __restrict__ freq, const float* __restrict__ dec) {
    int d = blockIdx.x;
    int n = threadIdx.x;
    double rho = -exp((double)dec[n]);
    double th  = (double)freq[n];
    double mag = exp(rho * (double)d);
    double ph  = th * (double)d;
    g_kre[d * NS + n] = (float)(mag * cos(ph));
    g_kim[d * NS + n] = (float)(mag * sin(ph));
    if (d == 0 && n == 0) g_pad[0] = 0;   // keep g_pad resident (layout pin)
}

// ---------------- projection planes: single fp16, [n][k] ----------------
__global__ void __launch_bounds__(256) prep_planes(const float* __restrict__ pin,
                                                   const float* __restrict__ pout) {
    int idx = blockIdx.x * 256 + threadIdx.x;   // 0..131071
    if (idx < NS * Hdim) {                      // pin: [n<64][k<1024]
        int n = idx >> 10, k = idx & 1023;
        g_pinF[idx] = __half_as_ushort(__float2half(pin[(size_t)k * NS + n]));
    } else {                                    // pout: [n<1024][k<64]
        int j = idx - NS * Hdim;
        int n = j >> 6, k = j & 63;
        g_poutF[j] = __half_as_ushort(__float2half(pout[(size_t)k * Hdim + n]));
    }
}

#define RS 80   // gemmA: 64B data + 16B pad

// ============ GEMM A (HMMA fp16 1-term): g_u[M,64] = input[M,1024] @ P_in[1024,64] ============
// smem: Af(10240) Bf(5120) = 15360 static
__global__ void __launch_bounds__(256) gemmA_mma(const float* __restrict__ A) {
    __shared__ char sm[15360];
    char* Af = sm;
    char* Bf = sm + 10240;

    int tid = threadIdx.x;
    int m0  = blockIdx.x * 128;
    int w   = tid >> 5, l = tid & 31;
    int wm  = w >> 1, wn = w & 1;          // warp tile 32m x 32n
    int lr  = l >> 2, lc = l & 3;
    int lrow = l & 15, lhalf = (l >> 4) * 16;

    int ra[4], qa[4];
#pragma unroll
    for (int t = 0; t < 4; ++t) { int idx = t * 256 + tid; ra[t] = idx >> 3; qa[t] = idx & 7; }
    int rB = tid >> 2, qB = tid & 3;

    uint32_t smb = cvta_smem(sm);

    float acc[2][4][4];
#pragma unroll
    for (int i = 0; i < 2; i++)
#pragma unroll
        for (int j = 0; j < 4; j++)
#pragma unroll
            for (int q = 0; q < 4; q++) acc[i][j][q] = 0.f;

    // prologue: prefetch chunk 0
    float4 areg[4];
    uint4 bfreg;
#pragma unroll
    for (int t = 0; t < 4; ++t)
        areg[t] = *(const float4*)&A[(size_t)(m0 + ra[t]) * Hdim + qa[t] * 4];
    bfreg = *(const uint4*)&g_pinF[rB * Hdim + qB * 8];

    for (int c = 0; c < 32; ++c) {
        // STS current chunk (single fp16 plane)
#pragma unroll
        for (int t = 0; t < 4; ++t) {
            uint32_t p01 = pack2h(__float2half(areg[t].x), __float2half(areg[t].y));
            uint32_t p23 = pack2h(__float2half(areg[t].z), __float2half(areg[t].w));
            *(uint2*)(Af + ra[t] * RS + qa[t] * 8) = make_uint2(p01, p23);
        }
        *(uint4*)(Bf + rB * RS + qB * 16) = bfreg;
        __syncthreads();

        // prefetch next chunk (overlaps with MMA below)
        if (c < 31) {
            int k1 = (c + 1) * 32;
#pragma unroll
            for (int t = 0; t < 4; ++t)
                areg[t] = *(const float4*)&A[(size_t)(m0 + ra[t]) * Hdim + k1 + qa[t] * 4];
            bfreg = *(const uint4*)&g_pinF[rB * Hdim + k1 + qB * 8];
        }

#pragma unroll
        for (int ks = 0; ks < 2; ++ks) {
            int kb = ks * 32;
            uint32_t af[2][4];
#pragma unroll
            for (int mt = 0; mt < 2; ++mt) {
                uint32_t off = (uint32_t)((wm * 32 + mt * 16 + lrow) * RS + kb + lhalf);
                ldsm_x4(af[mt], smb + off);
            }
#pragma unroll
            for (int nt = 0; nt < 4; ++nt) {
                int n0 = wn * 32 + nt * 8 + lr;
                int co = kb + lc * 4;
                uint32_t bf[2];
                bf[0] = *(const uint32_t*)(Bf + n0 * RS + co);
                bf[1] = *(const uint32_t*)(Bf + n0 * RS + co + 16);
#pragma unroll
                for (int mt = 0; mt < 2; ++mt)
                    mma16816h(acc[mt][nt], af[mt], bf);
            }
        }
        __syncthreads();
    }
#pragma unroll
    for (int mt = 0; mt < 2; ++mt) {
        size_t mrow = (size_t)m0 + wm * 32 + mt * 16 + lr;
#pragma unroll
        for (int nt = 0; nt < 4; ++nt) {
            int n = wn * 32 + nt * 8 + lc * 2;
            *(float2*)&g_u[mrow * NS + n]       = make_float2(acc[mt][nt][0], acc[mt][nt][1]);
            *(float2*)&g_u[(mrow + 8) * NS + n] = make_float2(acc[mt][nt][2], acc[mt][nt][3]);
        }
    }
}

// ---------------- FIR (NTAP=48, TL=64) -> single fp16 plane; folded final-state ----------------
#define TL  64
#define WIN (TL + NTAP)   // 112 rows
__global__ void __launch_bounds__(256) fir_kernel(const float* __restrict__ init_state,
                                                  float* __restrict__ outp, int mode) {
    __shared__ float us[WIN * NS];
    int b    = blockIdx.x >> 7;
    int lblk = blockIdx.x & 127;
    int l0   = lblk * TL;
    int base_i = (l0 + 1) - (NTAP - 1);
    int tid  = threadIdx.x;

    for (int idx = tid; idx < WIN * NS; idx += 256) {
        int row = idx >> 6;
        int n   = idx & 63;
        int i   = base_i + row;
        float v;
        if (i < 0)        v = 0.f;
        else if (i == 0)  v = init_state[b * NS + n];
        else              v = g_u[((size_t)b * Lseq + (i - 1)) * NS + n];
        us[idx] = v;
    }
    __syncthreads();

    int n  = tid & 63;
    int lt = tid >> 6;
#pragma unroll
    for (int g = 0; g < 2; ++g) {
        int lb  = lt * 16 + g * 8;
        int off = lb + NTAP - 1;
        float acc[8];
#pragma unroll
        for (int r = 0; r < 8; r++) acc[r] = 0.f;
#pragma unroll
        for (int dc = 0; dc < NTAP; dc += 8) {
            float kk[8];
#pragma unroll
            for (int t = 0; t < 8; t++) kk[t] = g_kre[(dc + t) * NS + n];
            float uu[15];
#pragma unroll
            for (int t = 0; t < 15; t++) uu[t] = us[(off - dc - 7 + t) * NS + n];
#pragma unroll
            for (int d = 0; d < 8; ++d)
#pragma unroll
                for (int r = 0; r < 8; r++) acc[r] += kk[d] * uu[7 + r - d];
        }
#pragma unroll
        for (int r = 0; r < 8; r++) {
            size_t o = ((size_t)b * Lseq + l0 + lb + r) * NS + n;
            g_ch[o] = __half_as_ushort(__float2half(acc[r]));
        }
    }

    // folded final state s_L (complex) -> tail of d_out (full fp32 path)
    if (lblk == 127 && mode != 0 && tid < 64) {
        float re = 0.f, im = 0.f;
#pragma unroll 4
        for (int d = 0; d < NTAP; ++d) {
            float u = us[(Lseq - d - base_i) * NS + tid];
            re += g_kre[d * NS + tid] * u;
            im += g_kim[d * NS + tid] * u;
        }
        float* base = outp + (size_t)M_TOT * Hdim;
        if (mode == 2) {
            base[((size_t)b * NS + tid) * 2 + 0] = re;
            base[((size_t)b * NS + tid) * 2 + 1] = im;
        } else {
            base[(size_t)b * NS + tid] = re;
        }
    }
}

// ============ GEMM B (HMMA fp16 1-term, single K-pass): out = conv @ P_out ============
// smem: Af(18432) Bf(18432) = 36864; RS2=144
#define RS2 144
#define GB_SMEM (2 * 128 * RS2)   // 36864
__global__ void __launch_bounds__(256, 2) gemmB_mma(float* __restrict__ C) {
    extern __shared__ char dsm[];
    int tid = threadIdx.x;
    int n0c = blockIdx.x * 128;
    int m0  = blockIdx.y * 128;
    int w   = tid >> 5, l = tid & 31;
    int wm  = w >> 1, wn = w & 1;          // warp tile 32m x 64n
    int lr  = l >> 2, lc = l & 3;
    int lrow = l & 15, lhalf = (l >> 4) * 16;

    char* Af = dsm;
    char* Bf = dsm + 18432;
    uint32_t smb = cvta_smem(dsm);

    float acc[2][8][4];
#pragma unroll
    for (int i = 0; i < 2; i++)
#pragma unroll
        for (int j = 0; j < 8; j++)
#pragma unroll
            for (int q = 0; q < 4; q++) acc[i][j][q] = 0.f;

    // staging: full K=64; pure uint4 copies (2 planes)
#pragma unroll
    for (int t = 0; t < 4; ++t) {
        int idx = t * 256 + tid;
        int r = idx >> 3, q = idx & 7;
        *(uint4*)(Af + r * RS2 + q * 16) = *(const uint4*)&g_ch[(size_t)(m0 + r) * NS + q * 8];
        *(uint4*)(Bf + r * RS2 + q * 16) = *(const uint4*)&g_poutF[(size_t)(n0c + r) * NS + q * 8];
    }
    __syncthreads();

#pragma unroll
    for (int kstep = 0; kstep < 4; ++kstep) {
        int kb = kstep * 32;   // byte offset of 16-element k group
        uint32_t af[2][4];
#pragma unroll
        for (int mt = 0; mt < 2; ++mt) {
            uint32_t off = (uint32_t)((wm * 32 + mt * 16 + lrow) * RS2 + kb + lhalf);
            ldsm_x4(af[mt], smb + off);
        }
#pragma unroll
        for (int nt = 0; nt < 8; ++nt) {
            int n0 = wn * 64 + nt * 8 + lr;
            int co = kb + lc * 4;
            uint32_t bf[2];
            bf[0] = *(const uint32_t*)(Bf + n0 * RS2 + co);
            bf[1] = *(const uint32_t*)(Bf + n0 * RS2 + co + 16);
#pragma unroll
            for (int mt = 0; mt < 2; ++mt)
                mma16816h(acc[mt][nt], af[mt], bf);
        }
    }
#pragma unroll
    for (int mt = 0; mt < 2; ++mt) {
        size_t mrow = (size_t)m0 + wm * 32 + mt * 16 + lr;
#pragma unroll
        for (int nt = 0; nt < 8; ++nt) {
            int n = n0c + wn * 64 + nt * 8 + lc * 2;
            *(float2*)&C[mrow * Hdim + n]       = make_float2(acc[mt][nt][0], acc[mt][nt][1]);
            *(float2*)&C[(mrow + 8) * Hdim + n] = make_float2(acc[mt][nt][2], acc[mt][nt][3]);
        }
    }
}

// ---------------- launch ----------------
extern "C" void kernel_launch(void* const* d_in, const int* in_sizes, int n_in,
                              void* d_out, int out_size) {
    const float* input = (const float*)d_in[0];
    const float* init  = (const float*)d_in[1];
    const float* pin   = (const float*)d_in[2];
    const float* pout  = (const float*)d_in[3];
    const float* freq  = (const float*)d_in[4];
    const float* dec   = (const float*)d_in[5];
    float* out = (float*)d_out;

    cudaFuncSetAttribute(gemmB_mma, cudaFuncAttributeMaxDynamicSharedMemorySize, GB_SMEM);

    long long tail = (long long)out_size - (long long)M_TOT * Hdim;
    int mode = 0;
    if (tail >= (long long)Bsz * NS * 2)  mode = 2;
    else if (tail >= (long long)Bsz * NS) mode = 1;

    taps_kernel<<<NTAP, NS>>>(freq, dec);
    prep_planes<<<512, 256>>>(pin, pout);
    gemmA_mma<<<M_TOT / 128, 256>>>(input);
    fir_kernel<<<Bsz * (Lseq / TL), 256>>>(init, out, mode);
    gemmB_mma<<<dim3(Hdim / 128, M_TOT / 128), 256, GB_SMEM>>>(out);
}

// round 17
// speedup vs baseline: 1.4329x; 1.1030x over previous
#include <cuda_runtime.h>
#include <cuda_fp16.h>
#include <math.h>
#include <stdint.h>

#define Bsz   8
#define Lseq  8192
#define Hdim  1024
#define NS    64
#define NTAP  48
#define M_TOT (Bsz * Lseq)   // 65536

typedef unsigned short ushort_t;

// ---------------- scratch ----------------
// LAYOUT IS LOAD-BEARING (L2 slice hash): do not move/resize these arrays.
__device__ float    g_u[(size_t)M_TOT * NS];        // 16 MB
__device__ ushort_t g_ch[(size_t)M_TOT * NS];       // 8 MB  conv (fp16 bits)
__device__ ushort_t g_pad[(size_t)M_TOT * NS];      // 8 MB  layout placeholder
__device__ ushort_t g_pinF[NS * Hdim];              // [n][k] fp16
__device__ ushort_t g_poutF[Hdim * NS];             // [n][k] fp16
__device__ float g_kre[NTAP * NS];
__device__ float g_kim[NTAP * NS];

__device__ __forceinline__ uint32_t pack2h(__half a, __half b) {
    return (uint32_t)__half_as_ushort(a) | ((uint32_t)__half_as_ushort(b) << 16);
}
// f32.f16.f16.f32 HMMA (sm_80+, legal under compute_103)
__device__ __forceinline__ void mma16816h(float* c, const uint32_t* a, const uint32_t* b) {
    asm volatile(
        "mma.sync.aligned.m16n8k16.row.col.f32.f16.f16.f32 "
        "{%0,%1,%2,%3}, {%4,%5,%6,%7}, {%8,%9}, {%0,%1,%2,%3};"
        : "+f"(c[0]), "+f"(c[1]), "+f"(c[2]), "+f"(c[3])
        : "r"(a[0]), "r"(a[1]), "r"(a[2]), "r"(a[3]), "r"(b[0]), "r"(b[1]));
}
__device__ __forceinline__ uint32_t cvta_smem(const void* p) {
    uint32_t a;
    asm("{ .reg .u64 t; cvta.to.shared.u64 t, %1; cvt.u32.u64 %0, t; }" : "=r"(a) : "l"(p));
    return a;
}
__device__ __forceinline__ void ldsm_x4(uint32_t* r, uint32_t addr) {
    asm volatile("ldmatrix.sync.aligned.m8n8.x4.shared.b16 {%0,%1,%2,%3}, [%4];"
                 : "=r"(r[0]), "=r"(r[1]), "=r"(r[2]), "=r"(r[3]) : "r"(addr));
}

// ---------------- taps ----------------
__global__ void taps_kernel(const float* __restrict__ freq, const float* __restrict__ dec) {
    int d = blockIdx.x;
    int n = threadIdx.x;
    double rho = -exp((double)dec[n]);
    double th  = (double)freq[n];
    double mag = exp(rho * (double)d);
    double ph  = th * (double)d;
    g_kre[d * NS + n] = (float)(mag * cos(ph));
    g_kim[d * NS + n] = (float)(mag * sin(ph));
    if (d == 0 && n == 0) g_pad[0] = 0;   // keep g_pad resident (layout pin)
}

// ---------------- projection planes: single fp16, [n][k] ----------------
__global__ void __launch_bounds__(256) prep_planes(const float* __restrict__ pin,
                                                   const float* __restrict__ pout) {
    int idx = blockIdx.x * 256 + threadIdx.x;   // 0..131071
    if (idx < NS * Hdim) {                      // pin: [n<64][k<1024]
        int n = idx >> 10, k = idx & 1023;
        g_pinF[idx] = __half_as_ushort(__float2half(pin[(size_t)k * NS + n]));
    } else {                                    // pout: [n<1024][k<64]
        int j = idx - NS * Hdim;
        int n = j >> 6, k = j & 63;
        g_poutF[j] = __half_as_ushort(__float2half(pout[(size_t)k * Hdim + n]));
    }
}

#define RSA 144   // gemmA rows: 128B data (64 fp16 k) + 16B pad

// ============ GEMM A (HMMA fp16 1-term, K-chunk 64): g_u = input @ P_in ============
// smem: Af(128*144=18432) Bf(64*144=9216) = 27648 static; 16 chunks, 2 syncs each
__global__ void __launch_bounds__(256) gemmA_mma(const float* __restrict__ A) {
    __shared__ char sm[27648];
    char* Af = sm;
    char* Bf = sm + 18432;

    int tid = threadIdx.x;
    int m0  = blockIdx.x * 128;
    int w   = tid >> 5, l = tid & 31;
    int wm  = w >> 1, wn = w & 1;          // warp tile 32m x 32n
    int lr  = l >> 2, lc = l & 3;
    int lrow = l & 15, lhalf = (l >> 4) * 16;

    // A staging: 2048 float4 per chunk, 8/thread; 16 float4 per row
    int ra[8], qa[8];
#pragma unroll
    for (int t = 0; t < 8; ++t) { int idx = t * 256 + tid; ra[t] = idx >> 4; qa[t] = idx & 15; }
    // B staging: 512 uint4 per chunk, 2/thread; 8 uint4 per row
    int rB[2], qB[2];
#pragma unroll
    for (int t = 0; t < 2; ++t) { int idx = t * 256 + tid; rB[t] = idx >> 3; qB[t] = idx & 7; }

    uint32_t smb = cvta_smem(sm);

    float acc[2][4][4];
#pragma unroll
    for (int i = 0; i < 2; i++)
#pragma unroll
        for (int j = 0; j < 4; j++)
#pragma unroll
            for (int q = 0; q < 4; q++) acc[i][j][q] = 0.f;

    // prologue: prefetch chunk 0
    float4 areg[8];
    uint4 bfreg[2];
#pragma unroll
    for (int t = 0; t < 8; ++t)
        areg[t] = *(const float4*)&A[(size_t)(m0 + ra[t]) * Hdim + qa[t] * 4];
#pragma unroll
    for (int t = 0; t < 2; ++t)
        bfreg[t] = *(const uint4*)&g_pinF[rB[t] * Hdim + qB[t] * 8];

    for (int c = 0; c < 16; ++c) {
        // STS current chunk
#pragma unroll
        for (int t = 0; t < 8; ++t) {
            uint32_t p01 = pack2h(__float2half(areg[t].x), __float2half(areg[t].y));
            uint32_t p23 = pack2h(__float2half(areg[t].z), __float2half(areg[t].w));
            *(uint2*)(Af + ra[t] * RSA + qa[t] * 8) = make_uint2(p01, p23);
        }
#pragma unroll
        for (int t = 0; t < 2; ++t)
            *(uint4*)(Bf + rB[t] * RSA + qB[t] * 16) = bfreg[t];
        __syncthreads();

        // prefetch next chunk (overlaps with MMA below)
        if (c < 15) {
            int k1 = (c + 1) * 64;
#pragma unroll
            for (int t = 0; t < 8; ++t)
                areg[t] = *(const float4*)&A[(size_t)(m0 + ra[t]) * Hdim + k1 + qa[t] * 4];
#pragma unroll
            for (int t = 0; t < 2; ++t)
                bfreg[t] = *(const uint4*)&g_pinF[rB[t] * Hdim + k1 + qB[t] * 8];
        }

#pragma unroll
        for (int ks = 0; ks < 4; ++ks) {
            int kb = ks * 32;
            uint32_t af[2][4];
#pragma unroll
            for (int mt = 0; mt < 2; ++mt) {
                uint32_t off = (uint32_t)((wm * 32 + mt * 16 + lrow) * RSA + kb + lhalf);
                ldsm_x4(af[mt], smb + off);
            }
#pragma unroll
            for (int nt = 0; nt < 4; ++nt) {
                int n0 = wn * 32 + nt * 8 + lr;
                int co = kb + lc * 4;
                uint32_t bf[2];
                bf[0] = *(const uint32_t*)(Bf + n0 * RSA + co);
                bf[1] = *(const uint32_t*)(Bf + n0 * RSA + co + 16);
#pragma unroll
                for (int mt = 0; mt < 2; ++mt)
                    mma16816h(acc[mt][nt], af[mt], bf);
            }
        }
        __syncthreads();
    }
#pragma unroll
    for (int mt = 0; mt < 2; ++mt) {
        size_t mrow = (size_t)m0 + wm * 32 + mt * 16 + lr;
#pragma unroll
        for (int nt = 0; nt < 4; ++nt) {
            int n = wn * 32 + nt * 8 + lc * 2;
            *(float2*)&g_u[mrow * NS + n]       = make_float2(acc[mt][nt][0], acc[mt][nt][1]);
            *(float2*)&g_u[(mrow + 8) * NS + n] = make_float2(acc[mt][nt][2], acc[mt][nt][3]);
        }
    }
}

// ---------------- FIR (NTAP=48, TL=64, merged 16-row window) ----------------
#define TL  64
#define WIN (TL + NTAP)   // 112 rows
__global__ void __launch_bounds__(256) fir_kernel(const float* __restrict__ init_state,
                                                  float* __restrict__ outp, int mode) {
    __shared__ float us[WIN * NS];
    int b    = blockIdx.x >> 7;
    int lblk = blockIdx.x & 127;
    int l0   = lblk * TL;
    int base_i = (l0 + 1) - (NTAP - 1);
    int tid  = threadIdx.x;

    for (int idx = tid; idx < WIN * NS; idx += 256) {
        int row = idx >> 6;
        int n   = idx & 63;
        int i   = base_i + row;
        float v;
        if (i < 0)        v = 0.f;
        else if (i == 0)  v = init_state[b * NS + n];
        else              v = g_u[((size_t)b * Lseq + (i - 1)) * NS + n];
        us[idx] = v;
    }
    __syncthreads();

    int n  = tid & 63;
    int lt = tid >> 6;
    int lb = lt * 16;               // 16 output rows per thread
    int off0 = lb + NTAP - 1;       // smem row for (r=0, d=0)

    float acc[16];
#pragma unroll
    for (int r = 0; r < 16; r++) acc[r] = 0.f;

#pragma unroll
    for (int dc = 0; dc < NTAP; dc += 8) {
        float kk[8];
#pragma unroll
        for (int t = 0; t < 8; t++) kk[t] = g_kre[(dc + t) * NS + n];
        float uu[23];   // union window rows [off0-dc-7 .. off0-dc+15]
#pragma unroll
        for (int t = 0; t < 23; t++) uu[t] = us[(off0 - dc - 7 + t) * NS + n];
#pragma unroll
        for (int d = 0; d < 8; ++d)
#pragma unroll
            for (int r = 0; r < 16; r++) acc[r] += kk[d] * uu[7 + r - d];
    }
#pragma unroll
    for (int r = 0; r < 16; r++) {
        size_t o = ((size_t)b * Lseq + l0 + lb + r) * NS + n;
        g_ch[o] = __half_as_ushort(__float2half(acc[r]));
    }

    // folded final state s_L (complex) -> tail of d_out (full fp32 path)
    if (lblk == 127 && mode != 0 && tid < 64) {
        float re = 0.f, im = 0.f;
#pragma unroll 4
        for (int d = 0; d < NTAP; ++d) {
            float u = us[(Lseq - d - base_i) * NS + tid];
            re += g_kre[d * NS + tid] * u;
            im += g_kim[d * NS + tid] * u;
        }
        float* base = outp + (size_t)M_TOT * Hdim;
        if (mode == 2) {
            base[((size_t)b * NS + tid) * 2 + 0] = re;
            base[((size_t)b * NS + tid) * 2 + 1] = im;
        } else {
            base[(size_t)b * NS + tid] = re;
        }
    }
}

// ============ GEMM B (HMMA fp16 1-term, single K-pass): out = conv @ P_out ============
// smem: Af(18432) Bf(18432) = 36864; RS2=144
#define RS2 144
#define GB_SMEM (2 * 128 * RS2)   // 36864
__global__ void __launch_bounds__(256, 2) gemmB_mma(float* __restrict__ C) {
    extern __shared__ char dsm[];
    int tid = threadIdx.x;
    int n0c = blockIdx.x * 128;
    int m0  = blockIdx.y * 128;
    int w   = tid >> 5, l = tid & 31;
    int wm  = w >> 1, wn = w & 1;          // warp tile 32m x 64n
    int lr  = l >> 2, lc = l & 3;
    int lrow = l & 15, lhalf = (l >> 4) * 16;

    char* Af = dsm;
    char* Bf = dsm + 18432;
    uint32_t smb = cvta_smem(dsm);

    float acc[2][8][4];
#pragma unroll
    for (int i = 0; i < 2; i++)
#pragma unroll
        for (int j = 0; j < 8; j++)
#pragma unroll
            for (int q = 0; q < 4; q++) acc[i][j][q] = 0.f;

    // staging: full K=64; pure uint4 copies (2 planes)
#pragma unroll
    for (int t = 0; t < 4; ++t) {
        int idx = t * 256 + tid;
        int r = idx >> 3, q = idx & 7;
        *(uint4*)(Af + r * RS2 + q * 16) = *(const uint4*)&g_ch[(size_t)(m0 + r) * NS + q * 8];
        *(uint4*)(Bf + r * RS2 + q * 16) = *(const uint4*)&g_poutF[(size_t)(n0c + r) * NS + q * 8];
    }
    __syncthreads();

#pragma unroll
    for (int kstep = 0; kstep < 4; ++kstep) {
        int kb = kstep * 32;   // byte offset of 16-element k group
        uint32_t af[2][4];
#pragma unroll
        for (int mt = 0; mt < 2; ++mt) {
            uint32_t off = (uint32_t)((wm * 32 + mt * 16 + lrow) * RS2 + kb + lhalf);
            ldsm_x4(af[mt], smb + off);
        }
#pragma unroll
        for (int nt = 0; nt < 8; ++nt) {
            int n0 = wn * 64 + nt * 8 + lr;
            int co = kb + lc * 4;
            uint32_t bf[2];
            bf[0] = *(const uint32_t*)(Bf + n0 * RS2 + co);
            bf[1] = *(const uint32_t*)(Bf + n0 * RS2 + co + 16);
#pragma unroll
            for (int mt = 0; mt < 2; ++mt)
                mma16816h(acc[mt][nt], af[mt], bf);
        }
    }
#pragma unroll
    for (int mt = 0; mt < 2; ++mt) {
        size_t mrow = (size_t)m0 + wm * 32 + mt * 16 + lr;
#pragma unroll
        for (int nt = 0; nt < 8; ++nt) {
            int n = n0c + wn * 64 + nt * 8 + lc * 2;
            *(float2*)&C[mrow * Hdim + n]       = make_float2(acc[mt][nt][0], acc[mt][nt][1]);
            *(float2*)&C[(mrow + 8) * Hdim + n] = make_float2(acc[mt][nt][2], acc[mt][nt][3]);
        }
    }
}

// ---------------- launch ----------------
extern "C" void kernel_launch(void* const* d_in, const int* in_sizes, int n_in,
                              void* d_out, int out_size) {
    const float* input = (const float*)d_in[0];
    const float* init  = (const float*)d_in[1];
    const float* pin   = (const float*)d_in[2];
    const float* pout  = (const float*)d_in[3];
    const float* freq  = (const float*)d_in[4];
    const float* dec   = (const float*)d_in[5];
    float* out = (float*)d_out;

    cudaFuncSetAttribute(gemmB_mma, cudaFuncAttributeMaxDynamicSharedMemorySize, GB_SMEM);

    long long tail = (long long)out_size - (long long)M_TOT * Hdim;
    int mode = 0;
    if (tail >= (long long)Bsz * NS * 2)  mode = 2;
    else if (tail >= (long long)Bsz * NS) mode = 1;

    taps_kernel<<<NTAP, NS>>>(freq, dec);
    prep_planes<<<512, 256>>>(pin, pout);
    gemmA_mma<<<M_TOT / 128, 256>>>(input);
    fir_kernel<<<Bsz * (Lseq / TL), 256>>>(init, out, mode);
    gemmB_mma<<<dim3(Hdim / 128, M_TOT / 128), 256, GB_SMEM>>>(out);
}